// round 15
// baseline (speedup 1.0000x reference)
#include <cuda_runtime.h>
#include <cuda_bf16.h>
#include <math.h>
#include <stdint.h>

// ---------------------------------------------------------------------------
// Problem constants
// ---------------------------------------------------------------------------
#define G_NUM  1024
#define P_N    75
#define DEG_E  8
#define N_N    (G_NUM * P_N)
#define E_N    (N_N * DEG_E)
#define EPG    (P_N * DEG_E)          // 600 edges/graph
#define RPG    (EPG * 4)              // 2400 records/graph
#define KS_C   5
#define KK_C   25
#define NKEY   (P_N * KK_C)           // 1875 (k,dst) buckets
#define NOFF   (NKEY + 1)
#define YP     132                    // Y row stride (floats), 132 % 8 == 4
#define HQ     68                     // hcur row stride (floats), 68 % 8 == 4
#define NTC    320
#define WP32   20
#define WP64   36

// ---- smem layout (byte offsets) -------------------------------------------
#define SM_OFF2  0                    // ushort[NOFF]            3752
#define SM_DEG   3760                 // int[P_N]                 300
#define SM_HCUR  4064                 // float[80*HQ]           21760
#define SM_Y     25824                // float[80*YP]           42240
#define SM_W     68064                // u32[2*2*64*WP64]       36864
#define SM_C     104928               // slab(uint2) / W1 / head 9728
#define SM_TOTAL 114688

// bucket-phase aliases inside the Y region
#define BK_SWT   (SM_Y + 0)           // float[RPG]   9600
#define BK_CNT   (SM_Y + 9600)        // int[NKEY]    7500
#define BK_SDK   (SM_Y + 17100)       // float[NKEY]  7500
#define BK_KEY   (SM_Y + 24600)       // u16[RPG]     4800
#define BK_SSR   (SM_Y + 29400)       // u8[RPG]      2400
#define BK_PART  (SM_Y + 31800)       // int[240]      960
#define BK_XS    (SM_Y + 32760)       // float[80]     320

// ---------------------------------------------------------------------------
// Device scratch
// ---------------------------------------------------------------------------
__device__ __align__(16) uint2 d_rec[G_NUM * RPG];   // {w bits, src}, (k,dst)-sorted
__device__ __align__(16) unsigned d_W32hi[26 * 64 * WP32];
__device__ __align__(16) unsigned d_W32lo[26 * 64 * WP32];
__device__ __align__(16) unsigned d_W64hi[26 * 64 * WP64];
__device__ __align__(16) unsigned d_W64lo[26 * 64 * WP64];

__device__ __forceinline__ float elu_f(float v) { return v > 0.0f ? v : expm1f(v); }

__device__ __forceinline__ unsigned pk2(float a, float b) {
    __nv_bfloat162 t = __floats2bfloat162_rn(a, b);
    return reinterpret_cast<unsigned&>(t);
}
__device__ __forceinline__ float bhi(float v) {
    return __bfloat162float(__float2bfloat16(v));
}

__device__ __forceinline__ uint32_t smem_to_u32(const void* p) {
    uint32_t a;
    asm("{ .reg .u64 t; cvta.to.shared.u64 t, %1; cvt.u32.u64 %0, t; }"
        : "=r"(a) : "l"(p));
    return a;
}

// packed f32x2 helpers (sm_103a FFMA2 path)
__device__ __forceinline__ unsigned long long fma2(unsigned long long a,
                                                   unsigned long long b,
                                                   unsigned long long c) {
    unsigned long long d;
    asm("fma.rn.f32x2 %0, %1, %2, %3;" : "=l"(d) : "l"(a), "l"(b), "l"(c));
    return d;
}
__device__ __forceinline__ unsigned long long packf2(float x, float y) {
    unsigned long long r;
    asm("mov.b64 %0, {%1, %2};" : "=l"(r) : "f"(x), "f"(y));
    return r;
}
__device__ __forceinline__ void unpackf2(unsigned long long v, float& x, float& y) {
    asm("mov.b64 {%0, %1}, %2;" : "=f"(x), "=f"(y) : "l"(v));
}

#define CP_ASYNC16(dst, src) \
    asm volatile("cp.async.ca.shared.global [%0], [%1], 16;" \
                 :: "r"((uint32_t)(dst)), "l"(src) : "memory")
#define CP_ASYNC8(dst, src) \
    asm volatile("cp.async.ca.shared.global [%0], [%1], 8;" \
                 :: "r"((uint32_t)(dst)), "l"(src) : "memory")
#define CP_WAIT_ALL() asm volatile("cp.async.wait_all;" ::: "memory")

__device__ __forceinline__ void mma_bf16(float c[4], const unsigned a[4],
                                         unsigned b0, unsigned b1) {
    asm volatile(
        "mma.sync.aligned.m16n8k16.row.col.f32.bf16.bf16.f32 "
        "{%0,%1,%2,%3}, {%4,%5,%6,%7}, {%8,%9}, {%0,%1,%2,%3};"
        : "+f"(c[0]), "+f"(c[1]), "+f"(c[2]), "+f"(c[3])
        : "r"(a[0]), "r"(a[1]), "r"(a[2]), "r"(a[3]), "r"(b0), "r"(b1));
}

// ---------------------------------------------------------------------------
// Prep: split W (+root) into bf16 hi/lo, transposed [mat][o][ipair]
// ---------------------------------------------------------------------------
__global__ __launch_bounds__(256)
void prep_kernel(const float* __restrict__ W, const float* __restrict__ root,
                 unsigned* __restrict__ oHi, unsigned* __restrict__ oLo,
                 int I, int WPv) {
    const int mat = blockIdx.x;
    const float* Wp = (mat < KK_C) ? (W + mat * I * 64) : root;
    const int KHv = I / 2;
    for (int t = threadIdx.x; t < 64 * KHv; t += 256) {
        const int o = t & 63, ipair = t >> 6;
        float w0 = Wp[(2 * ipair) * 64 + o], w1 = Wp[(2 * ipair + 1) * 64 + o];
        float h0 = bhi(w0), h1 = bhi(w1);
        oHi[(mat * 64 + o) * WPv + ipair] = pk2(h0, h1);
        oLo[(mat * 64 + o) * WPv + ipair] = pk2(w0 - h0, w1 - h1);
    }
    for (int t = threadIdx.x; t < 64 * (WPv - KHv); t += 256) {
        const int o = t % 64, p = KHv + t / 64;
        oHi[(mat * 64 + o) * WPv + p] = 0;
        oLo[(mat * 64 + o) * WPv + p] = 0;
    }
}

// ---------------------------------------------------------------------------
// Conv phase (I in {32,64}): chunk = 2 mats; 3 independent mma chains;
// cp.async staging; uint2 records; software-pipelined f32x2 gather.
// ---------------------------------------------------------------------------
template<int I>
__device__ __forceinline__
void conv_phase(char* sm, uint32_t sm32, const unsigned* __restrict__ gWhi,
                const unsigned* __restrict__ gWlo, const float* __restrict__ bias,
                const uint2* __restrict__ grec, int tid) {
    constexpr int KH  = I / 2;
    constexpr int KST = I / 16;
    constexpr int WP  = KH + 4;
    constexpr int WCH = 2 * 64 * WP;

    unsigned short* off2 = (unsigned short*)(sm + SM_OFF2);
    int*            degS = (int*)(sm + SM_DEG);
    float*          hcur = (float*)(sm + SM_HCUR);
    float*          Ys   = (float*)(sm + SM_Y);
    unsigned*       wsHi = (unsigned*)(sm + SM_W);
    unsigned*       wsLo = wsHi + WCH;
    uint2*          slab = (uint2*)(sm + SM_C);

    const uint32_t wsHiA = sm32 + SM_W;
    const uint32_t wsLoA = wsHiA + WCH * 4;
    const uint32_t slabA = sm32 + SM_C;

    __syncthreads();   // hcur ready; Y/W/slab regions free

    // stage W chunk 0 via cp.async
    for (int t = tid; t < WCH / 4; t += NTC) {
        CP_ASYNC16(wsHiA + 16 * t, (const uint4*)gWhi + t);
        CP_ASYNC16(wsLoA + 16 * t, (const uint4*)gWlo + t);
    }

    const int w = tid >> 5, lane = tid & 31;
    const int gr = lane >> 2, cg = lane & 3;
    const int mt = w >> 1, matw = w & 1;
    const int r0 = mt * 16 + gr;
    const int d = tid >> 2, q = tid & 3;

    // A fragments straight from fp32 hcur (conflict-free HQ % 8 == 4)
    unsigned aHi[KST][4], aLo[KST][4];
    #pragma unroll
    for (int ks = 0; ks < KST; ks++) {
        const int p0 = ks * 8 + cg;
        float2 v00 = *(const float2*)(hcur + r0 * HQ + 2 * p0);
        float2 v10 = *(const float2*)(hcur + (r0 + 8) * HQ + 2 * p0);
        float2 v01 = *(const float2*)(hcur + r0 * HQ + 2 * p0 + 8);
        float2 v11 = *(const float2*)(hcur + (r0 + 8) * HQ + 2 * p0 + 8);
        float a, b;
        a = bhi(v00.x); b = bhi(v00.y);
        aHi[ks][0] = pk2(a, b); aLo[ks][0] = pk2(v00.x - a, v00.y - b);
        a = bhi(v10.x); b = bhi(v10.y);
        aHi[ks][1] = pk2(a, b); aLo[ks][1] = pk2(v10.x - a, v10.y - b);
        a = bhi(v01.x); b = bhi(v01.y);
        aHi[ks][2] = pk2(a, b); aLo[ks][2] = pk2(v01.x - a, v01.y - b);
        a = bhi(v11.x); b = bhi(v11.y);
        aHi[ks][3] = pk2(a, b); aLo[ks][3] = pk2(v11.x - a, v11.y - b);
    }
    CP_WAIT_ALL();
    __syncthreads();   // W0 staged

    unsigned long long agg2[8];
    #pragma unroll
    for (int j = 0; j < 8; j++) agg2[j] = 0ull;

    for (int c = 0; c < 13; c++) {
        // phase A: slab prefetch (cp.async uint2 records) + GEMM(c)
        const int base = off2[(2 * c) * P_N];
        const int endi = min((2 * c + 2) * P_N, NKEY);
        const int nrec = (int)off2[endi] - base;
        for (int t = tid; t < nrec; t += NTC)
            CP_ASYNC8(slabA + 8 * t, grec + base + t);

        #pragma unroll
        for (int j = 0; j < 8; j++) {
            const int n0 = j * 8;
            const unsigned* bh = wsHi + (matw * 64 + n0 + gr) * WP;
            const unsigned* bl = wsLo + (matw * 64 + n0 + gr) * WP;
            float Ca[4] = {0, 0, 0, 0}, Cb[4] = {0, 0, 0, 0}, Cc[4] = {0, 0, 0, 0};
            #pragma unroll
            for (int ks = 0; ks < KST; ks++) {
                const int p0 = ks * 8 + cg;
                const unsigned b0h = bh[p0], b1h = bh[p0 + 4];
                const unsigned b0l = bl[p0], b1l = bl[p0 + 4];
                mma_bf16(Ca, aHi[ks], b0h, b1h);
                mma_bf16(Cb, aLo[ks], b0h, b1h);
                mma_bf16(Cc, aHi[ks], b0l, b1l);
            }
            float* yp = Ys + r0 * YP + matw * 64 + n0 + 2 * cg;
            *(float2*)yp            = make_float2(Ca[0] + Cb[0] + Cc[0],
                                                  Ca[1] + Cb[1] + Cc[1]);
            *(float2*)(yp + 8 * YP) = make_float2(Ca[2] + Cb[2] + Cc[2],
                                                  Ca[3] + Cb[3] + Cc[3]);
        }
        CP_WAIT_ALL();
        __syncthreads();   // Y + slab ready; Ws free

        // phase B: stage W(c+1) + software-pipelined gather(c), f32x2 FMA
        if (c < 12) {
            const uint4* sH = (const uint4*)(gWhi + (2 * (c + 1)) * (64 * WP));
            const uint4* sL = (const uint4*)(gWlo + (2 * (c + 1)) * (64 * WP));
            for (int t = tid; t < WCH / 4; t += NTC) {
                CP_ASYNC16(wsHiA + 16 * t, sH + t);
                CP_ASYNC16(wsLoA + 16 * t, sL + t);
            }
        }
        if (d < P_N) {
            const int kmax = (c == 12) ? 1 : 2;
            const float* yq0 = Ys + q * 16;
            #pragma unroll
            for (int seg = 0; seg < 2; seg++) {
                if (seg == 1 && kmax == 1) break;
                const int gk = 2 * c + seg;
                int r        = (int)off2[gk * P_N + d] - base;
                const int hi = (int)off2[gk * P_N + d + 1] - base;
                const float* yq = yq0 + seg * 64;
                if (r < hi) {
                    uint2 rc = slab[r];
                    while (true) {
                        const float wv = __uint_as_float(rc.x);
                        const unsigned long long ww = packf2(wv, wv);
                        const ulonglong2* yp = (const ulonglong2*)(yq + (int)rc.y * YP);
                        ulonglong2 u0 = yp[0], u1 = yp[1], u2 = yp[2], u3 = yp[3];
                        ++r;
                        if (r < hi) rc = slab[r];
                        agg2[0] = fma2(ww, u0.x, agg2[0]);
                        agg2[1] = fma2(ww, u0.y, agg2[1]);
                        agg2[2] = fma2(ww, u1.x, agg2[2]);
                        agg2[3] = fma2(ww, u1.y, agg2[3]);
                        agg2[4] = fma2(ww, u2.x, agg2[4]);
                        agg2[5] = fma2(ww, u2.y, agg2[5]);
                        agg2[6] = fma2(ww, u3.x, agg2[6]);
                        agg2[7] = fma2(ww, u3.y, agg2[7]);
                        if (r >= hi) break;
                    }
                }
            }
        }
        CP_WAIT_ALL();
        __syncthreads();   // Ws(c+1) ready; gather done -> Y reusable
    }

    // epilogue: mean-scale + root (chunk 12, mat slot 1) + bias + ELU -> hcur
    if (d < P_N) {
        const float inv = 1.0f / (float)max(degS[d], 1);
        const float4* rt = (const float4*)(Ys + d * YP + 64 + q * 16);
        float* op = hcur + d * HQ + q * 16;
        #pragma unroll
        for (int jj = 0; jj < 4; jj++) {
            float4 r4 = rt[jj];
            float a0, a1, a2, a3;
            unpackf2(agg2[2 * jj],     a0, a1);
            unpackf2(agg2[2 * jj + 1], a2, a3);
            float4 o4;
            o4.x = elu_f(a0 * inv + r4.x + bias[q * 16 + 4 * jj + 0]);
            o4.y = elu_f(a1 * inv + r4.y + bias[q * 16 + 4 * jj + 1]);
            o4.z = elu_f(a2 * inv + r4.z + bias[q * 16 + 4 * jj + 2]);
            o4.w = elu_f(a3 * inv + r4.w + bias[q * 16 + 4 * jj + 3]);
            *(float4*)(op + 4 * jj) = o4;
        }
    }
    __syncthreads();
}

// ---------------------------------------------------------------------------
// Mega kernel: one CTA = one graph, end to end.
// ---------------------------------------------------------------------------
__global__ __launch_bounds__(NTC, 2)
void mega_kernel(const float* __restrict__ x, const int* __restrict__ eidx,
                 const float* __restrict__ eattr, const float* __restrict__ pos,
                 const float* __restrict__ W1, const float* __restrict__ root1,
                 const float* __restrict__ b1,
                 const unsigned* __restrict__ W32hi, const unsigned* __restrict__ W32lo,
                 const float* __restrict__ b2,
                 const unsigned* __restrict__ W64hi, const unsigned* __restrict__ W64lo,
                 const float* __restrict__ b3,
                 const float* __restrict__ fc1w, const float* __restrict__ fc1b,
                 const float* __restrict__ fc2w, const float* __restrict__ fc2b,
                 float* __restrict__ out) {
    extern __shared__ __align__(16) char sm[];
    const int g = blockIdx.x, tid = threadIdx.x;
    const uint32_t sm32 = smem_to_u32(sm);
    const int lane = tid & 31, wid5 = tid >> 5;

    unsigned short* off2 = (unsigned short*)(sm + SM_OFF2);
    int*            degS = (int*)(sm + SM_DEG);
    float*          hcur = (float*)(sm + SM_HCUR);
    float*          swt  = (float*)(sm + BK_SWT);
    int*            cnt  = (int*)(sm + BK_CNT);
    float*          sdk  = (float*)(sm + BK_SDK);
    unsigned short* skey = (unsigned short*)(sm + BK_KEY);
    unsigned char*  ssr  = (unsigned char*)(sm + BK_SSR);
    int*            part = (int*)(sm + BK_PART);
    float*          xs   = (float*)(sm + BK_XS);
    float*          W1s  = (float*)(sm + SM_C);
    float*          r1s  = (float*)(sm + SM_C + 3200);
    float*          b1s  = (float*)(sm + SM_C + 3328);

    // ---- init
    for (int t = tid; t < NKEY; t += NTC) { cnt[t] = 0; sdk[t] = 0.0f; }
    if (tid < P_N) { degS[tid] = 0; xs[tid] = x[g * P_N + tid]; }
    for (int t = tid; t < 5 * HQ; t += NTC) hcur[P_N * HQ + t] = 0.0f;
    for (int t = tid; t < KK_C * 32; t += NTC) W1s[t] = W1[t];
    if (tid < 32) { r1s[tid] = root1[tid]; b1s[tid] = b1[tid]; }
    __syncthreads();

    // ---- bucket: basis + records + counts + sdk (conv1 partial sums)
    for (int el = tid; el < EPG; el += NTC) {
        const int e  = g * EPG + el;
        const float u0 = eattr[2 * e], u1 = eattr[2 * e + 1];
        const int src = eidx[e]       - g * P_N;
        const int dst = eidx[E_N + e] - g * P_N;
        atomicAdd(&degS[dst], 1);
        float p0 = u0 * (KS_C - 1), p1 = u1 * (KS_C - 1);
        float l0 = fminf(fmaxf(floorf(p0), 0.0f), (float)(KS_C - 1));
        float l1 = fminf(fmaxf(floorf(p1), 0.0f), (float)(KS_C - 1));
        float f0 = p0 - l0, f1 = p1 - l1;
        int i00 = (int)l0, i01 = min(i00 + 1, KS_C - 1);
        int i10 = (int)l1, i11 = min(i10 + 1, KS_C - 1);
        const float wa[2] = {1.0f - f0, f0};  const int ia[2] = {i00, i01};
        const float wb[2] = {1.0f - f1, f1};  const int ib[2] = {i10, i11};
        const float xv = xs[src];
        #pragma unroll
        for (int a = 0; a < 2; a++)
            #pragma unroll
            for (int b = 0; b < 2; b++) {
                const int slot = el * 4 + a * 2 + b;
                const int k = ia[a] + KS_C * ib[b];
                const int key = k * P_N + dst;
                skey[slot] = (unsigned short)key;
                ssr [slot] = (unsigned char)src;
                const float wv = wa[a] * wb[b];
                swt [slot] = wv;
                atomicAdd(&cnt[key], 1);
                atomicAdd(&sdk[key], wv * xv);
            }
    }
    __syncthreads();

    // ---- scan: warp-shuffle two-level (235 8-bucket blocks)
    int sum8 = 0;
    if (tid < 235) {
        #pragma unroll
        for (int j = 0; j < 8; j++) {
            int idx = tid * 8 + j;
            if (idx < NKEY) sum8 += cnt[idx];
        }
    }
    int v = sum8;
    #pragma unroll
    for (int o = 1; o < 32; o <<= 1) {
        int t = __shfl_up_sync(0xFFFFFFFFu, v, o);
        if (lane >= o) v += t;
    }
    if (lane == 31) part[wid5] = v;
    __syncthreads();
    if (tid == 0) {
        int run = 0;
        #pragma unroll
        for (int i = 0; i < 10; i++) { int t = part[i]; part[i] = run; run += t; }
    }
    __syncthreads();
    if (tid < 235) {
        int base = (v - sum8) + part[wid5];
        #pragma unroll
        for (int j = 0; j < 8; j++) {
            int idx = tid * 8 + j;
            if (idx < NKEY) { int c2 = cnt[idx]; cnt[idx] = base; base += c2; }
        }
    }
    __syncthreads();
    for (int t = tid; t < NKEY; t += NTC) off2[t] = (unsigned short)cnt[t];
    if (tid == 0) off2[NKEY] = (unsigned short)RPG;
    __syncthreads();

    // ---- scatter records (uint2) to gmem + conv1 from sdk
    uint2* grm = d_rec + g * RPG;
    for (int slot = tid; slot < RPG; slot += NTC) {
        const int key = skey[slot];
        const int p = atomicAdd(&cnt[key], 1);
        grm[p] = make_uint2(__float_as_uint(swt[slot]), (unsigned)ssr[slot]);
    }
    for (int it = tid; it < P_N * 32; it += NTC) {
        const int d = it >> 5, o = it & 31;
        float acc = 0.0f;
        #pragma unroll
        for (int k = 0; k < KK_C; k++) acc += sdk[k * P_N + d] * W1s[k * 32 + o];
        const float inv = 1.0f / (float)max(degS[d], 1);
        hcur[d * HQ + o] = elu_f(acc * inv + xs[d] * r1s[o] + b1s[o]);
    }

    // ---- conv layers
    conv_phase<32>(sm, sm32, W32hi, W32lo, b2, grm, tid);
    conv_phase<64>(sm, sm32, W64hi, W64lo, b3, grm, tid);

    // ---- head
    int*   vox = (int*)(sm + SM_C);
    float* gx  = (float*)(sm + SM_C + 304);
    float* f1  = (float*)(sm + SM_C + 1328);
    float* lg  = (float*)(sm + SM_C + 1840);

    if (tid < P_N) {
        const float p0 = pos[(g * P_N + tid) * 2 + 0];
        const float p1 = pos[(g * P_N + tid) * 2 + 1];
        const int v0 = min(max((int)(p0 / 14.0f), 0), 1);
        const int v1 = min(max((int)(p1 / 14.0f), 0), 1);
        vox[tid] = v0 + 2 * v1;
    }
    __syncthreads();
    if (tid < 256) {
        const int v2 = tid >> 6, c = tid & 63;
        float m = -3.402823466e38f; bool found = false;
        for (int r = 0; r < P_N; r++)
            if (vox[r] == v2) { m = fmaxf(m, hcur[r * HQ + c]); found = true; }
        gx[v2 * 64 + c] = found ? m : 0.0f;
    }
    __syncthreads();
    if (tid < 128) {
        float a = fc1b[tid];
        #pragma unroll 8
        for (int i = 0; i < 256; i++) a = fmaf(gx[i], fc1w[i * 128 + tid], a);
        f1[tid] = elu_f(a);
    }
    __syncthreads();
    if (tid < 10) {
        float a = fc2b[tid];
        #pragma unroll 8
        for (int i = 0; i < 128; i++) a = fmaf(f1[i], fc2w[i * 10 + tid], a);
        lg[tid] = a;
    }
    __syncthreads();
    if (tid == 0) {
        float m = lg[0];
        for (int o = 1; o < 10; o++) m = fmaxf(m, lg[o]);
        float s = 0.0f;
        for (int o = 0; o < 10; o++) s += expf(lg[o] - m);
        const float lse = m + logf(s);
        for (int o = 0; o < 10; o++) out[g * 10 + o] = lg[o] - lse;
    }
}

// ---------------------------------------------------------------------------
// Launch
// ---------------------------------------------------------------------------
extern "C" void kernel_launch(void* const* d_in, const int* in_sizes, int n_in,
                              void* d_out, int out_size) {
    const float* x     = (const float*)d_in[0];
    const int*   eidx  = (const int*)  d_in[1];
    const float* eattr = (const float*)d_in[2];
    const float* pos   = (const float*)d_in[4];
    const float* W1    = (const float*)d_in[5];
    const float* root1 = (const float*)d_in[6];
    const float* b1    = (const float*)d_in[7];
    const float* W2    = (const float*)d_in[8];
    const float* root2 = (const float*)d_in[9];
    const float* b2    = (const float*)d_in[10];
    const float* W3    = (const float*)d_in[11];
    const float* root3 = (const float*)d_in[12];
    const float* b3    = (const float*)d_in[13];
    const float* fc1w  = (const float*)d_in[14];
    const float* fc1b  = (const float*)d_in[15];
    const float* fc2w  = (const float*)d_in[16];
    const float* fc2b  = (const float*)d_in[17];
    float* out = (float*)d_out;

    void *w32h = nullptr, *w32l = nullptr, *w64h = nullptr, *w64l = nullptr;
    cudaGetSymbolAddress(&w32h, d_W32hi);
    cudaGetSymbolAddress(&w32l, d_W32lo);
    cudaGetSymbolAddress(&w64h, d_W64hi);
    cudaGetSymbolAddress(&w64l, d_W64lo);

    cudaFuncSetAttribute(mega_kernel, cudaFuncAttributeMaxDynamicSharedMemorySize, SM_TOTAL);

    prep_kernel<<<26, 256>>>(W2, root2, (unsigned*)w32h, (unsigned*)w32l, 32, WP32);
    prep_kernel<<<26, 256>>>(W3, root3, (unsigned*)w64h, (unsigned*)w64l, 64, WP64);
    mega_kernel<<<G_NUM, NTC, SM_TOTAL>>>(
        x, eidx, eattr, pos, W1, root1, b1,
        (const unsigned*)w32h, (const unsigned*)w32l, b2,
        (const unsigned*)w64h, (const unsigned*)w64l, b3,
        fc1w, fc1b, fc2w, fc2b, out);
}

// round 17
// speedup vs baseline: 1.5301x; 1.5301x over previous
#include <cuda_runtime.h>
#include <cuda_bf16.h>
#include <math.h>
#include <stdint.h>

// ---------------------------------------------------------------------------
// Problem constants
// ---------------------------------------------------------------------------
#define G_NUM  1024
#define P_N    75
#define DEG_E  8
#define N_N    (G_NUM * P_N)
#define E_N    (N_N * DEG_E)
#define EPG    (P_N * DEG_E)          // 600 edges/graph
#define RPG    (EPG * 4)              // 2400 records/graph
#define KS_C   5
#define KK_C   25
#define NKEY   (P_N * KK_C)           // 1875 (k,dst) buckets
#define NOFF   (NKEY + 1)
#define YP     132                    // Y row stride (floats), 132 % 8 == 4
#define HQ     68                     // hcur row stride (floats), 68 % 8 == 4
#define NTC    320
#define WP32   20
#define WP64   36

// ---- smem layout (byte offsets) -------------------------------------------
#define SM_OFF2  0                    // ushort[NOFF]            3752
#define SM_DEG   3760                 // int[P_N]                 300
#define SM_HCUR  4064                 // float[80*HQ]           21760
#define SM_Y     25824                // float[80*YP]           42240
#define SM_W     68064                // u32[2*2*64*WP64]       36864
#define SM_C     104928               // slab(uint2) / W1 / head 9728
#define SM_TOTAL 114688

// bucket-phase aliases inside the Y region
#define BK_SWT   (SM_Y + 0)           // float[RPG]   9600
#define BK_CNT   (SM_Y + 9600)        // int[NKEY]    7500
#define BK_SDK   (SM_Y + 17100)       // float[NKEY]  7500
#define BK_KEY   (SM_Y + 24600)       // u16[RPG]     4800
#define BK_SSR   (SM_Y + 29400)       // u8[RPG]      2400
#define BK_PART  (SM_Y + 31800)       // int[240]      960
#define BK_XS    (SM_Y + 32760)       // float[80]     320

// ---------------------------------------------------------------------------
// Device scratch
// ---------------------------------------------------------------------------
__device__ __align__(16) uint2 d_rec[G_NUM * RPG];   // {w bits, src}, (k,dst)-sorted
__device__ __align__(16) unsigned d_W32hi[26 * 64 * WP32];
__device__ __align__(16) unsigned d_W32lo[26 * 64 * WP32];
__device__ __align__(16) unsigned d_W64hi[26 * 64 * WP64];
__device__ __align__(16) unsigned d_W64lo[26 * 64 * WP64];

__device__ __forceinline__ float elu_f(float v) { return v > 0.0f ? v : expm1f(v); }

__device__ __forceinline__ unsigned pk2(float a, float b) {
    __nv_bfloat162 t = __floats2bfloat162_rn(a, b);
    return reinterpret_cast<unsigned&>(t);
}
__device__ __forceinline__ float bhi(float v) {
    return __bfloat162float(__float2bfloat16(v));
}

__device__ __forceinline__ uint32_t smem_to_u32(const void* p) {
    uint32_t a;
    asm("{ .reg .u64 t; cvta.to.shared.u64 t, %1; cvt.u32.u64 %0, t; }"
        : "=r"(a) : "l"(p));
    return a;
}

#define CP_ASYNC16(dst, src) \
    asm volatile("cp.async.ca.shared.global [%0], [%1], 16;" \
                 :: "r"((uint32_t)(dst)), "l"(src) : "memory")
#define CP_ASYNC8(dst, src) \
    asm volatile("cp.async.ca.shared.global [%0], [%1], 8;" \
                 :: "r"((uint32_t)(dst)), "l"(src) : "memory")
#define CP_WAIT_ALL() asm volatile("cp.async.wait_all;" ::: "memory")

__device__ __forceinline__ void mma_bf16(float c[4], const unsigned a[4],
                                         unsigned b0, unsigned b1) {
    asm volatile(
        "mma.sync.aligned.m16n8k16.row.col.f32.bf16.bf16.f32 "
        "{%0,%1,%2,%3}, {%4,%5,%6,%7}, {%8,%9}, {%0,%1,%2,%3};"
        : "+f"(c[0]), "+f"(c[1]), "+f"(c[2]), "+f"(c[3])
        : "r"(a[0]), "r"(a[1]), "r"(a[2]), "r"(a[3]), "r"(b0), "r"(b1));
}

// ---------------------------------------------------------------------------
// Prep: split W (+root) into bf16 hi/lo, transposed [mat][o][ipair]
// ---------------------------------------------------------------------------
__global__ __launch_bounds__(256)
void prep_kernel(const float* __restrict__ W, const float* __restrict__ root,
                 unsigned* __restrict__ oHi, unsigned* __restrict__ oLo,
                 int I, int WPv) {
    const int mat = blockIdx.x;
    const float* Wp = (mat < KK_C) ? (W + mat * I * 64) : root;
    const int KHv = I / 2;
    for (int t = threadIdx.x; t < 64 * KHv; t += 256) {
        const int o = t & 63, ipair = t >> 6;
        float w0 = Wp[(2 * ipair) * 64 + o], w1 = Wp[(2 * ipair + 1) * 64 + o];
        float h0 = bhi(w0), h1 = bhi(w1);
        oHi[(mat * 64 + o) * WPv + ipair] = pk2(h0, h1);
        oLo[(mat * 64 + o) * WPv + ipair] = pk2(w0 - h0, w1 - h1);
    }
    for (int t = threadIdx.x; t < 64 * (WPv - KHv); t += 256) {
        const int o = t % 64, p = KHv + t / 64;
        oHi[(mat * 64 + o) * WPv + p] = 0;
        oLo[(mat * 64 + o) * WPv + p] = 0;
    }
}

// ---------------------------------------------------------------------------
// Conv phase (I in {32,64}): chunk = 2 mats; 3 independent mma chains;
// cp.async staging; uint2 records; software-pipelined gather (scalar FFMA).
// ---------------------------------------------------------------------------
template<int I>
__device__ __forceinline__
void conv_phase(char* sm, uint32_t sm32, const unsigned* __restrict__ gWhi,
                const unsigned* __restrict__ gWlo, const float* __restrict__ bias,
                const uint2* __restrict__ grec, int tid) {
    constexpr int KH  = I / 2;
    constexpr int KST = I / 16;
    constexpr int WP  = KH + 4;
    constexpr int WCH = 2 * 64 * WP;

    unsigned short* off2 = (unsigned short*)(sm + SM_OFF2);
    int*            degS = (int*)(sm + SM_DEG);
    float*          hcur = (float*)(sm + SM_HCUR);
    float*          Ys   = (float*)(sm + SM_Y);
    unsigned*       wsHi = (unsigned*)(sm + SM_W);
    unsigned*       wsLo = wsHi + WCH;
    uint2*          slab = (uint2*)(sm + SM_C);

    const uint32_t wsHiA = sm32 + SM_W;
    const uint32_t wsLoA = wsHiA + WCH * 4;
    const uint32_t slabA = sm32 + SM_C;

    __syncthreads();   // hcur ready; Y/W/slab regions free

    // stage W chunk 0 via cp.async
    for (int t = tid; t < WCH / 4; t += NTC) {
        CP_ASYNC16(wsHiA + 16 * t, (const uint4*)gWhi + t);
        CP_ASYNC16(wsLoA + 16 * t, (const uint4*)gWlo + t);
    }

    const int w = tid >> 5, lane = tid & 31;
    const int gr = lane >> 2, cg = lane & 3;
    const int mt = w >> 1, matw = w & 1;
    const int r0 = mt * 16 + gr;
    const int d = tid >> 2, q = tid & 3;

    // A fragments straight from fp32 hcur (conflict-free HQ % 8 == 4)
    unsigned aHi[KST][4], aLo[KST][4];
    #pragma unroll
    for (int ks = 0; ks < KST; ks++) {
        const int p0 = ks * 8 + cg;
        float2 v00 = *(const float2*)(hcur + r0 * HQ + 2 * p0);
        float2 v10 = *(const float2*)(hcur + (r0 + 8) * HQ + 2 * p0);
        float2 v01 = *(const float2*)(hcur + r0 * HQ + 2 * p0 + 8);
        float2 v11 = *(const float2*)(hcur + (r0 + 8) * HQ + 2 * p0 + 8);
        float a, b;
        a = bhi(v00.x); b = bhi(v00.y);
        aHi[ks][0] = pk2(a, b); aLo[ks][0] = pk2(v00.x - a, v00.y - b);
        a = bhi(v10.x); b = bhi(v10.y);
        aHi[ks][1] = pk2(a, b); aLo[ks][1] = pk2(v10.x - a, v10.y - b);
        a = bhi(v01.x); b = bhi(v01.y);
        aHi[ks][2] = pk2(a, b); aLo[ks][2] = pk2(v01.x - a, v01.y - b);
        a = bhi(v11.x); b = bhi(v11.y);
        aHi[ks][3] = pk2(a, b); aLo[ks][3] = pk2(v11.x - a, v11.y - b);
    }
    CP_WAIT_ALL();
    __syncthreads();   // W0 staged

    float agg[16];
    #pragma unroll
    for (int j = 0; j < 16; j++) agg[j] = 0.0f;

    for (int c = 0; c < 13; c++) {
        // phase A: slab prefetch (cp.async uint2 records) + GEMM(c)
        const int base = off2[(2 * c) * P_N];
        const int endi = min((2 * c + 2) * P_N, NKEY);
        const int nrec = (int)off2[endi] - base;
        for (int t = tid; t < nrec; t += NTC)
            CP_ASYNC8(slabA + 8 * t, grec + base + t);

        #pragma unroll
        for (int j = 0; j < 8; j++) {
            const int n0 = j * 8;
            const unsigned* bh = wsHi + (matw * 64 + n0 + gr) * WP;
            const unsigned* bl = wsLo + (matw * 64 + n0 + gr) * WP;
            float Ca[4] = {0, 0, 0, 0}, Cb[4] = {0, 0, 0, 0}, Cc[4] = {0, 0, 0, 0};
            #pragma unroll
            for (int ks = 0; ks < KST; ks++) {
                const int p0 = ks * 8 + cg;
                const unsigned b0h = bh[p0], b1h = bh[p0 + 4];
                const unsigned b0l = bl[p0], b1l = bl[p0 + 4];
                mma_bf16(Ca, aHi[ks], b0h, b1h);
                mma_bf16(Cb, aLo[ks], b0h, b1h);
                mma_bf16(Cc, aHi[ks], b0l, b1l);
            }
            float* yp = Ys + r0 * YP + matw * 64 + n0 + 2 * cg;
            *(float2*)yp            = make_float2(Ca[0] + Cb[0] + Cc[0],
                                                  Ca[1] + Cb[1] + Cc[1]);
            *(float2*)(yp + 8 * YP) = make_float2(Ca[2] + Cb[2] + Cc[2],
                                                  Ca[3] + Cb[3] + Cc[3]);
        }
        CP_WAIT_ALL();
        __syncthreads();   // Y + slab ready; Ws free

        // phase B: stage W(c+1) + software-pipelined gather(c)
        if (c < 12) {
            const uint4* sH = (const uint4*)(gWhi + (2 * (c + 1)) * (64 * WP));
            const uint4* sL = (const uint4*)(gWlo + (2 * (c + 1)) * (64 * WP));
            for (int t = tid; t < WCH / 4; t += NTC) {
                CP_ASYNC16(wsHiA + 16 * t, sH + t);
                CP_ASYNC16(wsLoA + 16 * t, sL + t);
            }
        }
        if (d < P_N) {
            const int kmax = (c == 12) ? 1 : 2;
            const float* yq0 = Ys + q * 16;
            #pragma unroll
            for (int seg = 0; seg < 2; seg++) {
                if (seg == 1 && kmax == 1) break;
                const int gk = 2 * c + seg;
                int r        = (int)off2[gk * P_N + d] - base;
                const int hi = (int)off2[gk * P_N + d + 1] - base;
                const float* yq = yq0 + seg * 64;
                if (r < hi) {
                    uint2 rc = slab[r];
                    while (true) {
                        const float wv = __uint_as_float(rc.x);
                        const float4* yp = (const float4*)(yq + (int)rc.y * YP);
                        float4 v0 = yp[0], v1 = yp[1], v2 = yp[2], v3 = yp[3];
                        ++r;
                        if (r < hi) rc = slab[r];
                        agg[0]  = fmaf(wv, v0.x, agg[0]);  agg[1]  = fmaf(wv, v0.y, agg[1]);
                        agg[2]  = fmaf(wv, v0.z, agg[2]);  agg[3]  = fmaf(wv, v0.w, agg[3]);
                        agg[4]  = fmaf(wv, v1.x, agg[4]);  agg[5]  = fmaf(wv, v1.y, agg[5]);
                        agg[6]  = fmaf(wv, v1.z, agg[6]);  agg[7]  = fmaf(wv, v1.w, agg[7]);
                        agg[8]  = fmaf(wv, v2.x, agg[8]);  agg[9]  = fmaf(wv, v2.y, agg[9]);
                        agg[10] = fmaf(wv, v2.z, agg[10]); agg[11] = fmaf(wv, v2.w, agg[11]);
                        agg[12] = fmaf(wv, v3.x, agg[12]); agg[13] = fmaf(wv, v3.y, agg[13]);
                        agg[14] = fmaf(wv, v3.z, agg[14]); agg[15] = fmaf(wv, v3.w, agg[15]);
                        if (r >= hi) break;
                    }
                }
            }
        }
        CP_WAIT_ALL();
        __syncthreads();   // Ws(c+1) ready; gather done -> Y reusable
    }

    // epilogue: mean-scale + root (chunk 12, mat slot 1) + bias + ELU -> hcur
    if (d < P_N) {
        const float inv = 1.0f / (float)max(degS[d], 1);
        const float4* rt = (const float4*)(Ys + d * YP + 64 + q * 16);
        float* op = hcur + d * HQ + q * 16;
        #pragma unroll
        for (int jj = 0; jj < 4; jj++) {
            float4 r4 = rt[jj];
            float4 o4;
            o4.x = elu_f(agg[4 * jj + 0] * inv + r4.x + bias[q * 16 + 4 * jj + 0]);
            o4.y = elu_f(agg[4 * jj + 1] * inv + r4.y + bias[q * 16 + 4 * jj + 1]);
            o4.z = elu_f(agg[4 * jj + 2] * inv + r4.z + bias[q * 16 + 4 * jj + 2]);
            o4.w = elu_f(agg[4 * jj + 3] * inv + r4.w + bias[q * 16 + 4 * jj + 3]);
            *(float4*)(op + 4 * jj) = o4;
        }
    }
    __syncthreads();
}

// ---------------------------------------------------------------------------
// Mega kernel: one CTA = one graph, end to end.
// ---------------------------------------------------------------------------
__global__ __launch_bounds__(NTC, 2)
void mega_kernel(const float* __restrict__ x, const int* __restrict__ eidx,
                 const float* __restrict__ eattr, const float* __restrict__ pos,
                 const float* __restrict__ W1, const float* __restrict__ root1,
                 const float* __restrict__ b1,
                 const unsigned* __restrict__ W32hi, const unsigned* __restrict__ W32lo,
                 const float* __restrict__ b2,
                 const unsigned* __restrict__ W64hi, const unsigned* __restrict__ W64lo,
                 const float* __restrict__ b3,
                 const float* __restrict__ fc1w, const float* __restrict__ fc1b,
                 const float* __restrict__ fc2w, const float* __restrict__ fc2b,
                 float* __restrict__ out) {
    extern __shared__ __align__(16) char sm[];
    const int g = blockIdx.x, tid = threadIdx.x;
    const uint32_t sm32 = smem_to_u32(sm);
    const int lane = tid & 31, wid5 = tid >> 5;

    unsigned short* off2 = (unsigned short*)(sm + SM_OFF2);
    int*            degS = (int*)(sm + SM_DEG);
    float*          hcur = (float*)(sm + SM_HCUR);
    float*          swt  = (float*)(sm + BK_SWT);
    int*            cnt  = (int*)(sm + BK_CNT);
    float*          sdk  = (float*)(sm + BK_SDK);
    unsigned short* skey = (unsigned short*)(sm + BK_KEY);
    unsigned char*  ssr  = (unsigned char*)(sm + BK_SSR);
    int*            part = (int*)(sm + BK_PART);
    float*          xs   = (float*)(sm + BK_XS);
    float*          W1s  = (float*)(sm + SM_C);
    float*          r1s  = (float*)(sm + SM_C + 3200);
    float*          b1s  = (float*)(sm + SM_C + 3328);

    // ---- init
    for (int t = tid; t < NKEY; t += NTC) { cnt[t] = 0; sdk[t] = 0.0f; }
    if (tid < P_N) { degS[tid] = 0; xs[tid] = x[g * P_N + tid]; }
    for (int t = tid; t < 5 * HQ; t += NTC) hcur[P_N * HQ + t] = 0.0f;
    for (int t = tid; t < KK_C * 32; t += NTC) W1s[t] = W1[t];
    if (tid < 32) { r1s[tid] = root1[tid]; b1s[tid] = b1[tid]; }
    __syncthreads();

    // ---- bucket: basis + records + counts + sdk (conv1 partial sums)
    for (int el = tid; el < EPG; el += NTC) {
        const int e  = g * EPG + el;
        const float u0 = eattr[2 * e], u1 = eattr[2 * e + 1];
        const int src = eidx[e]       - g * P_N;
        const int dst = eidx[E_N + e] - g * P_N;
        atomicAdd(&degS[dst], 1);
        float p0 = u0 * (KS_C - 1), p1 = u1 * (KS_C - 1);
        float l0 = fminf(fmaxf(floorf(p0), 0.0f), (float)(KS_C - 1));
        float l1 = fminf(fmaxf(floorf(p1), 0.0f), (float)(KS_C - 1));
        float f0 = p0 - l0, f1 = p1 - l1;
        int i00 = (int)l0, i01 = min(i00 + 1, KS_C - 1);
        int i10 = (int)l1, i11 = min(i10 + 1, KS_C - 1);
        const float wa[2] = {1.0f - f0, f0};  const int ia[2] = {i00, i01};
        const float wb[2] = {1.0f - f1, f1};  const int ib[2] = {i10, i11};
        const float xv = xs[src];
        #pragma unroll
        for (int a = 0; a < 2; a++)
            #pragma unroll
            for (int b = 0; b < 2; b++) {
                const int slot = el * 4 + a * 2 + b;
                const int k = ia[a] + KS_C * ib[b];
                const int key = k * P_N + dst;
                skey[slot] = (unsigned short)key;
                ssr [slot] = (unsigned char)src;
                const float wv = wa[a] * wb[b];
                swt [slot] = wv;
                atomicAdd(&cnt[key], 1);
                atomicAdd(&sdk[key], wv * xv);
            }
    }
    __syncthreads();

    // ---- scan: warp-shuffle two-level (235 8-bucket blocks)
    int sum8 = 0;
    if (tid < 235) {
        #pragma unroll
        for (int j = 0; j < 8; j++) {
            int idx = tid * 8 + j;
            if (idx < NKEY) sum8 += cnt[idx];
        }
    }
    int v = sum8;
    #pragma unroll
    for (int o = 1; o < 32; o <<= 1) {
        int t = __shfl_up_sync(0xFFFFFFFFu, v, o);
        if (lane >= o) v += t;
    }
    if (lane == 31) part[wid5] = v;
    __syncthreads();
    if (tid == 0) {
        int run = 0;
        #pragma unroll
        for (int i = 0; i < 10; i++) { int t = part[i]; part[i] = run; run += t; }
    }
    __syncthreads();
    if (tid < 235) {
        int base = (v - sum8) + part[wid5];
        #pragma unroll
        for (int j = 0; j < 8; j++) {
            int idx = tid * 8 + j;
            if (idx < NKEY) { int c2 = cnt[idx]; cnt[idx] = base; base += c2; }
        }
    }
    __syncthreads();
    for (int t = tid; t < NKEY; t += NTC) off2[t] = (unsigned short)cnt[t];
    if (tid == 0) off2[NKEY] = (unsigned short)RPG;
    __syncthreads();

    // ---- scatter records (uint2) to gmem + conv1 from sdk
    uint2* grm = d_rec + g * RPG;
    for (int slot = tid; slot < RPG; slot += NTC) {
        const int key = skey[slot];
        const int p = atomicAdd(&cnt[key], 1);
        grm[p] = make_uint2(__float_as_uint(swt[slot]), (unsigned)ssr[slot]);
    }
    for (int it = tid; it < P_N * 32; it += NTC) {
        const int d = it >> 5, o = it & 31;
        float acc = 0.0f;
        #pragma unroll
        for (int k = 0; k < KK_C; k++) acc += sdk[k * P_N + d] * W1s[k * 32 + o];
        const float inv = 1.0f / (float)max(degS[d], 1);
        hcur[d * HQ + o] = elu_f(acc * inv + xs[d] * r1s[o] + b1s[o]);
    }

    // ---- conv layers
    conv_phase<32>(sm, sm32, W32hi, W32lo, b2, grm, tid);
    conv_phase<64>(sm, sm32, W64hi, W64lo, b3, grm, tid);

    // ---- head
    int*   vox = (int*)(sm + SM_C);
    float* gx  = (float*)(sm + SM_C + 304);
    float* f1  = (float*)(sm + SM_C + 1328);
    float* lg  = (float*)(sm + SM_C + 1840);

    if (tid < P_N) {
        const float p0 = pos[(g * P_N + tid) * 2 + 0];
        const float p1 = pos[(g * P_N + tid) * 2 + 1];
        const int v0 = min(max((int)(p0 / 14.0f), 0), 1);
        const int v1 = min(max((int)(p1 / 14.0f), 0), 1);
        vox[tid] = v0 + 2 * v1;
    }
    __syncthreads();
    if (tid < 256) {
        const int v2 = tid >> 6, c = tid & 63;
        float m = -3.402823466e38f; bool found = false;
        for (int r = 0; r < P_N; r++)
            if (vox[r] == v2) { m = fmaxf(m, hcur[r * HQ + c]); found = true; }
        gx[v2 * 64 + c] = found ? m : 0.0f;
    }
    __syncthreads();
    if (tid < 128) {
        float a = fc1b[tid];
        #pragma unroll 8
        for (int i = 0; i < 256; i++) a = fmaf(gx[i], fc1w[i * 128 + tid], a);
        f1[tid] = elu_f(a);
    }
    __syncthreads();
    if (tid < 10) {
        float a = fc2b[tid];
        #pragma unroll 8
        for (int i = 0; i < 128; i++) a = fmaf(f1[i], fc2w[i * 10 + tid], a);
        lg[tid] = a;
    }
    __syncthreads();
    if (tid == 0) {
        float m = lg[0];
        for (int o = 1; o < 10; o++) m = fmaxf(m, lg[o]);
        float s = 0.0f;
        for (int o = 0; o < 10; o++) s += expf(lg[o] - m);
        const float lse = m + logf(s);
        for (int o = 0; o < 10; o++) out[g * 10 + o] = lg[o] - lse;
    }
}

// ---------------------------------------------------------------------------
// Launch
// ---------------------------------------------------------------------------
extern "C" void kernel_launch(void* const* d_in, const int* in_sizes, int n_in,
                              void* d_out, int out_size) {
    const float* x     = (const float*)d_in[0];
    const int*   eidx  = (const int*)  d_in[1];
    const float* eattr = (const float*)d_in[2];
    const float* pos   = (const float*)d_in[4];
    const float* W1    = (const float*)d_in[5];
    const float* root1 = (const float*)d_in[6];
    const float* b1    = (const float*)d_in[7];
    const float* W2    = (const float*)d_in[8];
    const float* root2 = (const float*)d_in[9];
    const float* b2    = (const float*)d_in[10];
    const float* W3    = (const float*)d_in[11];
    const float* root3 = (const float*)d_in[12];
    const float* b3    = (const float*)d_in[13];
    const float* fc1w  = (const float*)d_in[14];
    const float* fc1b  = (const float*)d_in[15];
    const float* fc2w  = (const float*)d_in[16];
    const float* fc2b  = (const float*)d_in[17];
    float* out = (float*)d_out;

    void *w32h = nullptr, *w32l = nullptr, *w64h = nullptr, *w64l = nullptr;
    cudaGetSymbolAddress(&w32h, d_W32hi);
    cudaGetSymbolAddress(&w32l, d_W32lo);
    cudaGetSymbolAddress(&w64h, d_W64hi);
    cudaGetSymbolAddress(&w64l, d_W64lo);

    cudaFuncSetAttribute(mega_kernel, cudaFuncAttributeMaxDynamicSharedMemorySize, SM_TOTAL);

    prep_kernel<<<26, 256>>>(W2, root2, (unsigned*)w32h, (unsigned*)w32l, 32, WP32);
    prep_kernel<<<26, 256>>>(W3, root3, (unsigned*)w64h, (unsigned*)w64l, 64, WP64);
    mega_kernel<<<G_NUM, NTC, SM_TOTAL>>>(
        x, eidx, eattr, pos, W1, root1, b1,
        (const unsigned*)w32h, (const unsigned*)w32l, b2,
        (const unsigned*)w64h, (const unsigned*)w64l, b3,
        fc1w, fc1b, fc2w, fc2b, out);
}